// round 7
// baseline (speedup 1.0000x reference)
#include <cuda_runtime.h>
#include <cstddef>

// ---------------------------------------------------------------------------
// DWReg2DDecode3D: grid_sample -> upsample GEMM -> 4x(pool -> spiral gather
// -> tf32-split tensor GEMM+relu) -> head dsconv.  B=16, SP=9.
// ---------------------------------------------------------------------------

#define B 16
#define SP 9

typedef unsigned long long ull;

// scratch (device globals; no allocations allowed)
__device__ float g_gs[B * 64 * 256];          // grid-sampled feats
__device__ float g_bufB[12845056];            // conv outputs   (max 16*3136*256)
__device__ float g_bufA[25690112];            // pool outputs   (max 16*12544*128)
__device__ float g_bufC[25690112];            // gathered y     (same max)

// ---------------- packed f32x2 helpers (sm_10x FFMA2 path) -----------------
__device__ __forceinline__ void fma2(ull& d, ull a, ull b) {
    asm("fma.rn.f32x2 %0, %1, %2, %0;" : "+l"(d) : "l"(a), "l"(b));
}
__device__ __forceinline__ ull pack2(float a, float b) {
    ull u;
    asm("mov.b64 %0, {%1, %2};" : "=l"(u) : "f"(a), "f"(b));
    return u;
}
__device__ __forceinline__ float2 unpk(ull u) {
    float2 r;
    asm("mov.b64 {%0, %1}, %2;" : "=f"(r.x), "=f"(r.y) : "l"(u));
    return r;
}

// ---------------- tf32 helpers ---------------------------------------------
__device__ __forceinline__ unsigned cvt_tf32(float x) {
    unsigned r;
    asm("cvt.rna.tf32.f32 %0, %1;" : "=r"(r) : "f"(x));
    return r;
}
__device__ __forceinline__ void split_tf32(float v, unsigned& h, unsigned& l) {
    h = cvt_tf32(v);
    l = cvt_tf32(v - __uint_as_float(h));
}
__device__ __forceinline__ void mma_tf32(float4& c, const unsigned* a,
                                         const unsigned* b) {
    asm("mma.sync.aligned.m16n8k8.row.col.f32.tf32.tf32.f32 "
        "{%0,%1,%2,%3}, {%4,%5,%6,%7}, {%8,%9}, {%0,%1,%2,%3};"
        : "+f"(c.x), "+f"(c.y), "+f"(c.z), "+f"(c.w)
        : "r"(a[0]), "r"(a[1]), "r"(a[2]), "r"(a[3]), "r"(b[0]), "r"(b[1]));
}

// ---------------- grid sample (bilinear, align_corners, zero pad) ----------
__global__ void __launch_bounds__(256)
k_gridsample(const float* __restrict__ uv, const float* __restrict__ feat,
             float* __restrict__ gs)
{
    const int b = blockIdx.x, c = threadIdx.x;
    const float* fb = feat + ((size_t)b * 256 + c) * 16;
    for (int p = 0; p < 64; ++p) {
        float gx = (uv[((size_t)b * 64 + p) * 2 + 0] - 0.5f) * 2.f;
        float gy = (uv[((size_t)b * 64 + p) * 2 + 1] - 0.5f) * 2.f;
        gx = fminf(fmaxf(gx, -1.f), 1.f);
        gy = fminf(fmaxf(gy, -1.f), 1.f);
        float x = (gx + 1.f) * 0.5f * 3.f;
        float y = (gy + 1.f) * 0.5f * 3.f;
        float x0f = floorf(x), y0f = floorf(y);
        int x0 = (int)x0f, y0 = (int)y0f;
        int x1 = x0 + 1, y1 = y0 + 1;
        float fx = x - x0f, fy = y - y0f;
        float wa = (1.f - fx) * (1.f - fy);
        float wb = (1.f - fx) * fy;
        float wc = fx * (1.f - fy);
        float wd = fx * fy;
        float Ia = (x0 >= 0 && x0 < 4 && y0 >= 0 && y0 < 4) ? fb[y0 * 4 + x0] : 0.f;
        float Ib = (x0 >= 0 && x0 < 4 && y1 >= 0 && y1 < 4) ? fb[y1 * 4 + x0] : 0.f;
        float Ic = (x1 >= 0 && x1 < 4 && y0 >= 0 && y0 < 4) ? fb[y0 * 4 + x1] : 0.f;
        float Id = (x1 >= 0 && x1 < 4 && y1 >= 0 && y1 < 4) ? fb[y1 * 4 + x1] : 0.f;
        gs[((size_t)b * 64 + p) * 256 + c] = Ia * wa + Ib * wb + Ic * wc + Id * wd;
    }
}

// ---------------- upsample GEMM: out[b,v,c] = sum_p up[v,p]*gs[b,p,c] ------
__global__ void __launch_bounds__(256)
k_upsample(const float* __restrict__ up, const float* __restrict__ gs,
           float* __restrict__ out)
{
    constexpr int VT = 16;
    __shared__ float up_s[VT][64];
    const int b = blockIdx.y, v0 = blockIdx.x * VT, c = threadIdx.x;
    for (int t = threadIdx.x; t < VT * 64; t += 256)
        up_s[t / 64][t % 64] = up[(size_t)(v0 + t / 64) * 64 + (t % 64)];
    __syncthreads();
    float acc[VT];
#pragma unroll
    for (int i = 0; i < VT; ++i) acc[i] = 0.f;
    for (int p = 0; p < 64; ++p) {
        float g = gs[((size_t)b * 64 + p) * 256 + c];
#pragma unroll
        for (int i = 0; i < VT; ++i) acc[i] = fmaf(up_s[i][p], g, acc[i]);
    }
#pragma unroll
    for (int i = 0; i < VT; ++i)
        out[((size_t)b * 784 + v0 + i) * 256 + c] = acc[i];
}

// ---------------- mesh up-pool: out[b,n,c] = sum_k x[b,col[3n+k],c]*val ----
template <int Ci>
__global__ void __launch_bounds__(256)
k_pool(const float4* __restrict__ x, const int* __restrict__ col,
       const float* __restrict__ val, float4* __restrict__ out,
       int Nin, int Nout)
{
    constexpr int CQ = Ci / 4;
    constexpr int VPB = 256 / CQ;
    const int b = blockIdx.y;
    const int n = blockIdx.x * VPB + threadIdx.x / CQ;
    const int cq = threadIdx.x % CQ;
    if (n >= Nout) return;
    const int c0 = col[3 * n + 0], c1 = col[3 * n + 1], c2 = col[3 * n + 2];
    const float v0 = val[3 * n + 0], v1 = val[3 * n + 1], v2 = val[3 * n + 2];
    const float4* xb = x + (size_t)b * Nin * CQ;
    float4 a = xb[(size_t)c0 * CQ + cq];
    float4 bb = xb[(size_t)c1 * CQ + cq];
    float4 cc = xb[(size_t)c2 * CQ + cq];
    float4 r;
    r.x = a.x * v0 + bb.x * v1 + cc.x * v2;
    r.y = a.y * v0 + bb.y * v1 + cc.y * v2;
    r.z = a.z * v0 + bb.z * v1 + cc.z * v2;
    r.w = a.w * v0 + bb.w * v1 + cc.w * v2;
    out[((size_t)b * Nout + n) * CQ + cq] = r;
}

// ---------------- spiral gather + depthwise: y[v][ci]=sum_s x[idx]*dw ------
template <int Ci>
__global__ void __launch_bounds__(256)
k_gather(const float* __restrict__ x, const int* __restrict__ idx,
         const float* __restrict__ dw, float* __restrict__ y, int N)
{
    constexpr int VT = 32;
    constexpr int TPV = Ci / 4;
    constexpr int VG = 256 / TPV;
    constexpr int VCH = VT / VG;
    __shared__ int idx_s[VT * SP];
    const int b = blockIdx.y;
    const int n0 = blockIdx.x * VT;
    const int tid = threadIdx.x;

    for (int t = tid; t < VT * SP; t += 256)
        idx_s[t] = idx[(size_t)n0 * SP + t];
    __syncthreads();

    const int cq = (tid % TPV) * 4;
    const int vlo = (tid / TPV) * VCH;

    ull dw01[SP], dw23[SP];
#pragma unroll
    for (int s = 0; s < SP; ++s) {
        dw01[s] = pack2(__ldg(&dw[(size_t)(cq + 0) * SP + s]),
                        __ldg(&dw[(size_t)(cq + 1) * SP + s]));
        dw23[s] = pack2(__ldg(&dw[(size_t)(cq + 2) * SP + s]),
                        __ldg(&dw[(size_t)(cq + 3) * SP + s]));
    }
    const float* xb = x + ((size_t)b * N) * Ci + cq;
    float* yb = y + ((size_t)b * N + n0) * Ci + cq;
#pragma unroll 2
    for (int v = vlo; v < vlo + VCH; ++v) {
        const int* iv = idx_s + v * SP;
        ull a01 = 0ull, a23 = 0ull;
#pragma unroll
        for (int s = 0; s < SP; ++s) {
            float4 xv = *reinterpret_cast<const float4*>(
                xb + (size_t)iv[s] * Ci);
            fma2(a01, pack2(xv.x, xv.y), dw01[s]);
            fma2(a23, pack2(xv.z, xv.w), dw23[s]);
        }
        float2 r01 = unpk(a01), r23 = unpk(a23);
        *reinterpret_cast<float4*>(yb + (size_t)v * Ci) =
            make_float4(r01.x, r01.y, r23.x, r23.y);
    }
}

// ---------------- tf32-split tensor GEMM: C = relu(A[M,K] @ Bw[K,Co]) ------
// 256 thr = 8 warps (4M x 2N); warp tile 32 x TN/2; m16n8k8 tf32 mma.
// 2-term split: C = Ah*Bh + Ah*Bl + Al*Bh  (fp32 accumulate, err ~2^-22).
template <int K, int TN>
__global__ void __launch_bounds__(256)
k_gemm_mma(const float* __restrict__ A, const float* __restrict__ Bw,
           float* __restrict__ C, int Co)
{
    constexpr int TM = 128;
    constexpr int KK = 16;
    constexpr int NC = K / KK;
    constexpr int AST = TM + 8;
    constexpr int BST = TN + 8;
    constexpr int NT = TN / 16;          // n-tiles (8 cols each) per warp
    constexpr int AF4 = TM * KK / 1024;  // per-thread A float4 loads (2)
    constexpr int BF4 = TN * KK / 1024;  // per-thread B float4 loads (2 or 1)

    __shared__ unsigned Ah_s[KK][AST], Al_s[KK][AST];
    __shared__ unsigned Bh_s[KK][BST], Bl_s[KK][BST];

    const int tid = threadIdx.x;
    const int lane = tid & 31;
    const int w = tid >> 5;
    const int wm = w >> 1;           // 0..3
    const int wn = w & 1;            // 0..1
    const int m0 = blockIdx.x * TM;
    const int n0 = blockIdx.y * TN;

    float4 ar[AF4], br[BF4];

    auto loadA = [&](int kk) {
#pragma unroll
        for (int i = 0; i < AF4; ++i) {
            const int id = tid + i * 256;
            const int m = id >> 2, kq = id & 3;
            ar[i] = *reinterpret_cast<const float4*>(
                A + (size_t)(m0 + m) * K + kk + kq * 4);
        }
    };
    auto loadB = [&](int kk) {
#pragma unroll
        for (int i = 0; i < BF4; ++i) {
            const int id = tid + i * 256;
            const int r = id / (TN / 4), cq = id % (TN / 4);
            br[i] = *reinterpret_cast<const float4*>(
                Bw + (size_t)(kk + r) * Co + n0 + cq * 4);
        }
    };
    auto storeAB = [&]() {
#pragma unroll
        for (int i = 0; i < AF4; ++i) {
            const int id = tid + i * 256;
            const int m = id >> 2, kq = id & 3;
            const float vv[4] = {ar[i].x, ar[i].y, ar[i].z, ar[i].w};
#pragma unroll
            for (int j = 0; j < 4; ++j) {
                unsigned h, l;
                split_tf32(vv[j], h, l);
                Ah_s[kq * 4 + j][m] = h;
                Al_s[kq * 4 + j][m] = l;
            }
        }
#pragma unroll
        for (int i = 0; i < BF4; ++i) {
            const int id = tid + i * 256;
            const int r = id / (TN / 4), cq = id % (TN / 4);
            const float vv[4] = {br[i].x, br[i].y, br[i].z, br[i].w};
#pragma unroll
            for (int j = 0; j < 4; ++j) {
                unsigned h, l;
                split_tf32(vv[j], h, l);
                Bh_s[r][cq * 4 + j] = h;
                Bl_s[r][cq * 4 + j] = l;
            }
        }
    };

    float4 acc[2][NT];
#pragma unroll
    for (int mt = 0; mt < 2; ++mt)
#pragma unroll
        for (int nt = 0; nt < NT; ++nt)
            acc[mt][nt] = make_float4(0.f, 0.f, 0.f, 0.f);

    const int lk = lane & 3;         // k offset within frag
    const int lr = lane >> 2;        // row/col offset within frag

    loadA(0); loadB(0);
    for (int c = 0; c < NC; ++c) {
        __syncthreads();
        storeAB();
        __syncthreads();
        if (c + 1 < NC) { loadA((c + 1) * KK); loadB((c + 1) * KK); }
#pragma unroll
        for (int ks = 0; ks < KK; ks += 8) {
            unsigned bh[NT][2], bl[NT][2];
#pragma unroll
            for (int nt = 0; nt < NT; ++nt) {
                const int nb = wn * (TN / 2) + nt * 8 + lr;
                bh[nt][0] = Bh_s[ks + lk][nb];
                bh[nt][1] = Bh_s[ks + 4 + lk][nb];
                bl[nt][0] = Bl_s[ks + lk][nb];
                bl[nt][1] = Bl_s[ks + 4 + lk][nb];
            }
            unsigned ah[2][4], al[2][4];
#pragma unroll
            for (int mt = 0; mt < 2; ++mt) {
                const int mb = wm * 32 + mt * 16 + lr;
                ah[mt][0] = Ah_s[ks + lk][mb];
                ah[mt][1] = Ah_s[ks + lk][mb + 8];
                ah[mt][2] = Ah_s[ks + 4 + lk][mb];
                ah[mt][3] = Ah_s[ks + 4 + lk][mb + 8];
                al[mt][0] = Al_s[ks + lk][mb];
                al[mt][1] = Al_s[ks + lk][mb + 8];
                al[mt][2] = Al_s[ks + 4 + lk][mb];
                al[mt][3] = Al_s[ks + 4 + lk][mb + 8];
            }
#pragma unroll
            for (int mt = 0; mt < 2; ++mt)
#pragma unroll
                for (int nt = 0; nt < NT; ++nt) {
                    mma_tf32(acc[mt][nt], ah[mt], bh[nt]);
                    mma_tf32(acc[mt][nt], ah[mt], bl[nt]);
                    mma_tf32(acc[mt][nt], al[mt], bh[nt]);
                }
        }
    }

#pragma unroll
    for (int mt = 0; mt < 2; ++mt) {
        const int row = m0 + wm * 32 + mt * 16 + lr;
#pragma unroll
        for (int nt = 0; nt < NT; ++nt) {
            const int col = n0 + wn * (TN / 2) + nt * 8 + 2 * lk;
            float2 o0 = make_float2(fmaxf(acc[mt][nt].x, 0.f),
                                    fmaxf(acc[mt][nt].y, 0.f));
            float2 o1 = make_float2(fmaxf(acc[mt][nt].z, 0.f),
                                    fmaxf(acc[mt][nt].w, 0.f));
            *reinterpret_cast<float2*>(C + (size_t)row * Co + col) = o0;
            *reinterpret_cast<float2*>(C + (size_t)(row + 8) * Co + col) = o1;
        }
    }
}

// ---------------- head: Ci=64 -> Co=3, no relu -----------------------------
__global__ void __launch_bounds__(256)
k_head(const float* __restrict__ x, const int* __restrict__ idx,
       const float* __restrict__ dw, const float* __restrict__ pw,
       float* __restrict__ out, int N)
{
    constexpr int Ci = 64;
    constexpr int VT = 32;
    __shared__ float y_s[VT][Ci];
    __shared__ float pw_s[Ci * 3];
    __shared__ int idx_s[VT * SP];
    const int b = blockIdx.y, n0 = blockIdx.x * VT, tid = threadIdx.x;

    if (tid < Ci * 3) pw_s[tid] = pw[tid];
    for (int t = tid; t < VT * SP; t += 256)
        idx_s[t] = idx[(size_t)n0 * SP + t];
    __syncthreads();

    {
        const int ci = tid & (Ci - 1);
        const int vlo = (tid / Ci) * (VT / 4);
        float dwr[SP];
#pragma unroll
        for (int s = 0; s < SP; ++s) dwr[s] = __ldg(&dw[(size_t)ci * SP + s]);
        const float* xb = x + ((size_t)b * N) * Ci + ci;
#pragma unroll 2
        for (int v = vlo; v < vlo + VT / 4; ++v) {
            float acc = 0.f;
#pragma unroll
            for (int s = 0; s < SP; ++s)
                acc = fmaf(xb[(size_t)idx_s[v * SP + s] * Ci], dwr[s], acc);
            y_s[v][ci] = acc;
        }
    }
    __syncthreads();

    if (tid < VT * 3) {
        const int v = tid / 3, co = tid % 3;
        float acc = 0.f;
#pragma unroll
        for (int ci = 0; ci < Ci; ++ci)
            acc = fmaf(y_s[v][ci], pw_s[ci * 3 + co], acc);
        out[((size_t)b * N + n0 + v) * 3 + co] = acc;
    }
}

// ---------------------------------------------------------------------------
extern "C" void kernel_launch(void* const* d_in, const int* in_sizes, int n_in,
                              void* d_out, int out_size)
{
    const float* uv   = (const float*)d_in[0];
    const float* feat = (const float*)d_in[1];
    const float* up   = (const float*)d_in[2];
    const float* dw0  = (const float*)d_in[3];
    const float* pw0  = (const float*)d_in[4];
    const float* dw1  = (const float*)d_in[5];
    const float* pw1  = (const float*)d_in[6];
    const float* dw2  = (const float*)d_in[7];
    const float* pw2  = (const float*)d_in[8];
    const float* dw3  = (const float*)d_in[9];
    const float* pw3  = (const float*)d_in[10];
    const float* dwh  = (const float*)d_in[11];
    const float* pwh  = (const float*)d_in[12];

    // Resolve input ordering ambiguity via element counts.
    const float *upv0, *upv1, *upv2, *upv3;
    const int *spi0, *spi1, *spi2, *spi3, *upc0, *upc1, *upc2, *upc3;
    if (in_sizes[13] == 37632) {
        upv0 = (const float*)d_in[13]; upv1 = (const float*)d_in[14];
        upv2 = (const float*)d_in[15]; upv3 = (const float*)d_in[16];
        spi0 = (const int*)d_in[17]; spi1 = (const int*)d_in[18];
        spi2 = (const int*)d_in[19]; spi3 = (const int*)d_in[20];
        upc0 = (const int*)d_in[21]; upc1 = (const int*)d_in[22];
        upc2 = (const int*)d_in[23]; upc3 = (const int*)d_in[24];
    } else {
        spi0 = (const int*)d_in[13]; upc0 = (const int*)d_in[14]; upv0 = (const float*)d_in[15];
        spi1 = (const int*)d_in[16]; upc1 = (const int*)d_in[17]; upv1 = (const float*)d_in[18];
        spi2 = (const int*)d_in[19]; upc2 = (const int*)d_in[20]; upv2 = (const float*)d_in[21];
        spi3 = (const int*)d_in[22]; upc3 = (const int*)d_in[23]; upv3 = (const float*)d_in[24];
    }

    float *gsP, *bufA, *bufB, *bufC;
    cudaGetSymbolAddress((void**)&gsP, g_gs);
    cudaGetSymbolAddress((void**)&bufA, g_bufA);
    cudaGetSymbolAddress((void**)&bufB, g_bufB);
    cudaGetSymbolAddress((void**)&bufC, g_bufC);
    float* outp = (float*)d_out;

    // 1) grid sample -> gs (b,64,256)
    k_gridsample<<<B, 256>>>(uv, feat, gsP);
    // 2) upsample GEMM -> bufB (b,784,256)
    k_upsample<<<dim3(49, B), 256>>>(up, gsP, bufB);

    // stage 0: pool 784->1568, gather idx_3, GEMM 256->256 (dw0/pw0)
    k_pool<256><<<dim3(1568 / 4, B), 256>>>((const float4*)bufB, upc3, upv3,
                                            (float4*)bufA, 784, 1568);
    k_gather<256><<<dim3(1568 / 32, B), 256>>>(bufA, spi3, dw0, bufC, 1568);
    k_gemm_mma<256, 128><<<dim3(B * 1568 / 128, 2), 256>>>(bufC, pw0, bufB, 256);

    // stage 1: pool 1568->3136, gather idx_2, GEMM 256->256 (dw1/pw1)
    k_pool<256><<<dim3(3136 / 4, B), 256>>>((const float4*)bufB, upc2, upv2,
                                            (float4*)bufA, 1568, 3136);
    k_gather<256><<<dim3(3136 / 32, B), 256>>>(bufA, spi2, dw1, bufC, 3136);
    k_gemm_mma<256, 128><<<dim3(B * 3136 / 128, 2), 256>>>(bufC, pw1, bufB, 256);

    // stage 2: pool 3136->6272, gather idx_1, GEMM 256->128 (dw2/pw2)
    k_pool<256><<<dim3(6272 / 4, B), 256>>>((const float4*)bufB, upc1, upv1,
                                            (float4*)bufA, 3136, 6272);
    k_gather<256><<<dim3(6272 / 32, B), 256>>>(bufA, spi1, dw2, bufC, 6272);
    k_gemm_mma<256, 128><<<dim3(B * 6272 / 128, 1), 256>>>(bufC, pw2, bufB, 128);

    // stage 3: pool 6272->12544 (Ci=128), gather idx_0, GEMM 128->64 (dw3/pw3)
    k_pool<128><<<dim3(12544 / 8, B), 256>>>((const float4*)bufB, upc0, upv0,
                                             (float4*)bufA, 6272, 12544);
    k_gather<128><<<dim3(12544 / 32, B), 256>>>(bufA, spi0, dw3, bufC, 12544);
    k_gemm_mma<128, 64><<<dim3(B * 12544 / 128, 1), 256>>>(bufC, pw3, bufB, 64);

    // head: Ci=64 -> 3, no relu
    k_head<<<dim3(12544 / 32, B), 256>>>(bufB, spi0, dwh, pwh, outp, 12544);
}

// round 8
// speedup vs baseline: 1.2911x; 1.2911x over previous
#include <cuda_runtime.h>
#include <cuda_bf16.h>
#include <cstddef>

// ---------------------------------------------------------------------------
// DWReg2DDecode3D: grid_sample -> upsample GEMM -> 4x(pool -> spiral gather
// (bf16x2-split output) -> bf16 tensor GEMM+relu) -> head dsconv.  B=16,SP=9.
// ---------------------------------------------------------------------------

#define B 16
#define SP 9

typedef unsigned long long ull;
typedef __nv_bfloat16 bf16;

// scratch (device globals; no allocations allowed)
__device__ float g_gs[B * 64 * 256];          // grid-sampled feats
__device__ float g_bufB[12845056];            // conv outputs   (max 16*3136*256)
__device__ float g_bufA[25690112];            // pool outputs   (max 16*12544*128)
__device__ float g_bufC[25690112];            // gathered y, 2 bf16 planes
__device__ bf16  g_pwh[172032];               // pre-split pw high planes
__device__ bf16  g_pwl[172032];               // pre-split pw low planes

// ---------------- packed f32x2 helpers (sm_10x FFMA2 path) -----------------
__device__ __forceinline__ void fma2(ull& d, ull a, ull b) {
    asm("fma.rn.f32x2 %0, %1, %2, %0;" : "+l"(d) : "l"(a), "l"(b));
}
__device__ __forceinline__ ull pack2(float a, float b) {
    ull u;
    asm("mov.b64 %0, {%1, %2};" : "=l"(u) : "f"(a), "f"(b));
    return u;
}
__device__ __forceinline__ float2 unpk(ull u) {
    float2 r;
    asm("mov.b64 {%0, %1}, %2;" : "=f"(r.x), "=f"(r.y) : "l"(u));
    return r;
}

// ---------------- bf16 mma helpers -----------------------------------------
__device__ __forceinline__ void mma_bf16(float4& c, const unsigned* a,
                                         const unsigned* b) {
    asm("mma.sync.aligned.m16n8k16.row.col.f32.bf16.bf16.f32 "
        "{%0,%1,%2,%3}, {%4,%5,%6,%7}, {%8,%9}, {%0,%1,%2,%3};"
        : "+f"(c.x), "+f"(c.y), "+f"(c.z), "+f"(c.w)
        : "r"(a[0]), "r"(a[1]), "r"(a[2]), "r"(a[3]), "r"(b[0]), "r"(b[1]));
}
__device__ __forceinline__ void ldsm4(unsigned* r, const bf16* p) {
    unsigned a = (unsigned)__cvta_generic_to_shared(p);
    asm volatile("ldmatrix.sync.aligned.m8n8.x4.shared.b16 {%0,%1,%2,%3}, [%4];"
                 : "=r"(r[0]), "=r"(r[1]), "=r"(r[2]), "=r"(r[3]) : "r"(a));
}
__device__ __forceinline__ void ldsm4t(unsigned* r, const bf16* p) {
    unsigned a = (unsigned)__cvta_generic_to_shared(p);
    asm volatile("ldmatrix.sync.aligned.m8n8.x4.trans.shared.b16 {%0,%1,%2,%3}, [%4];"
                 : "=r"(r[0]), "=r"(r[1]), "=r"(r[2]), "=r"(r[3]) : "r"(a));
}
// split v -> (bf16 hi, bf16 lo) pair-packed words
__device__ __forceinline__ void split2(float a, float b, unsigned& h, unsigned& l) {
    bf16 ha = __float2bfloat16(a), hb = __float2bfloat16(b);
    bf16 la = __float2bfloat16(a - __bfloat162float(ha));
    bf16 lb = __float2bfloat16(b - __bfloat162float(hb));
    __nv_bfloat162 hh = __halves2bfloat162(ha, hb);
    __nv_bfloat162 ll = __halves2bfloat162(la, lb);
    h = *reinterpret_cast<unsigned*>(&hh);
    l = *reinterpret_cast<unsigned*>(&ll);
}

// ---------------- grid sample (bilinear, align_corners, zero pad) ----------
__global__ void __launch_bounds__(256)
k_gridsample(const float* __restrict__ uv, const float* __restrict__ feat,
             float* __restrict__ gs)
{
    const int b = blockIdx.x, c = threadIdx.x;
    const float* fb = feat + ((size_t)b * 256 + c) * 16;
    for (int p = 0; p < 64; ++p) {
        float gx = (uv[((size_t)b * 64 + p) * 2 + 0] - 0.5f) * 2.f;
        float gy = (uv[((size_t)b * 64 + p) * 2 + 1] - 0.5f) * 2.f;
        gx = fminf(fmaxf(gx, -1.f), 1.f);
        gy = fminf(fmaxf(gy, -1.f), 1.f);
        float x = (gx + 1.f) * 0.5f * 3.f;
        float y = (gy + 1.f) * 0.5f * 3.f;
        float x0f = floorf(x), y0f = floorf(y);
        int x0 = (int)x0f, y0 = (int)y0f;
        int x1 = x0 + 1, y1 = y0 + 1;
        float fx = x - x0f, fy = y - y0f;
        float wa = (1.f - fx) * (1.f - fy);
        float wb = (1.f - fx) * fy;
        float wc = fx * (1.f - fy);
        float wd = fx * fy;
        float Ia = (x0 >= 0 && x0 < 4 && y0 >= 0 && y0 < 4) ? fb[y0 * 4 + x0] : 0.f;
        float Ib = (x0 >= 0 && x0 < 4 && y1 >= 0 && y1 < 4) ? fb[y1 * 4 + x0] : 0.f;
        float Ic = (x1 >= 0 && x1 < 4 && y0 >= 0 && y0 < 4) ? fb[y0 * 4 + x1] : 0.f;
        float Id = (x1 >= 0 && x1 < 4 && y1 >= 0 && y1 < 4) ? fb[y1 * 4 + x1] : 0.f;
        gs[((size_t)b * 64 + p) * 256 + c] = Ia * wa + Ib * wb + Ic * wc + Id * wd;
    }
}

// ---------------- upsample GEMM: out[b,v,c] = sum_p up[v,p]*gs[b,p,c] ------
__global__ void __launch_bounds__(256)
k_upsample(const float* __restrict__ up, const float* __restrict__ gs,
           float* __restrict__ out)
{
    constexpr int VT = 16;
    __shared__ float up_s[VT][64];
    const int b = blockIdx.y, v0 = blockIdx.x * VT, c = threadIdx.x;
    for (int t = threadIdx.x; t < VT * 64; t += 256)
        up_s[t / 64][t % 64] = up[(size_t)(v0 + t / 64) * 64 + (t % 64)];
    __syncthreads();
    float acc[VT];
#pragma unroll
    for (int i = 0; i < VT; ++i) acc[i] = 0.f;
    for (int p = 0; p < 64; ++p) {
        float g = gs[((size_t)b * 64 + p) * 256 + c];
#pragma unroll
        for (int i = 0; i < VT; ++i) acc[i] = fmaf(up_s[i][p], g, acc[i]);
    }
#pragma unroll
    for (int i = 0; i < VT; ++i)
        out[((size_t)b * 784 + v0 + i) * 256 + c] = acc[i];
}

// ---------------- mesh up-pool ---------------------------------------------
template <int Ci>
__global__ void __launch_bounds__(256)
k_pool(const float4* __restrict__ x, const int* __restrict__ col,
       const float* __restrict__ val, float4* __restrict__ out,
       int Nin, int Nout)
{
    constexpr int CQ = Ci / 4;
    constexpr int VPB = 256 / CQ;
    const int b = blockIdx.y;
    const int n = blockIdx.x * VPB + threadIdx.x / CQ;
    const int cq = threadIdx.x % CQ;
    if (n >= Nout) return;
    const int c0 = col[3 * n + 0], c1 = col[3 * n + 1], c2 = col[3 * n + 2];
    const float v0 = val[3 * n + 0], v1 = val[3 * n + 1], v2 = val[3 * n + 2];
    const float4* xb = x + (size_t)b * Nin * CQ;
    float4 a = xb[(size_t)c0 * CQ + cq];
    float4 bb = xb[(size_t)c1 * CQ + cq];
    float4 cc = xb[(size_t)c2 * CQ + cq];
    float4 r;
    r.x = a.x * v0 + bb.x * v1 + cc.x * v2;
    r.y = a.y * v0 + bb.y * v1 + cc.y * v2;
    r.z = a.z * v0 + bb.z * v1 + cc.z * v2;
    r.w = a.w * v0 + bb.w * v1 + cc.w * v2;
    out[((size_t)b * Nout + n) * CQ + cq] = r;
}

// ---------------- pw pre-split: fp32 -> bf16 hi/lo planes ------------------
__global__ void __launch_bounds__(256)
k_splitw(const float* __restrict__ w, bf16* __restrict__ h,
         bf16* __restrict__ l, int n)
{
    const int i = blockIdx.x * 256 + threadIdx.x;
    if (i < n) {
        float v = w[i];
        bf16 hh = __float2bfloat16(v);
        h[i] = hh;
        l[i] = __float2bfloat16(v - __bfloat162float(hh));
    }
}

// ---------------- spiral gather + depthwise -> bf16x2 split planes ---------
template <int Ci>
__global__ void __launch_bounds__(256)
k_gather(const float* __restrict__ x, const int* __restrict__ idx,
         const float* __restrict__ dw, bf16* __restrict__ yh,
         bf16* __restrict__ yl, int N)
{
    constexpr int VT = 32;
    constexpr int TPV = Ci / 4;
    constexpr int VG = 256 / TPV;
    constexpr int VCH = VT / VG;
    __shared__ int idx_s[VT * SP];
    const int b = blockIdx.y;
    const int n0 = blockIdx.x * VT;
    const int tid = threadIdx.x;

    for (int t = tid; t < VT * SP; t += 256)
        idx_s[t] = idx[(size_t)n0 * SP + t];
    __syncthreads();

    const int cq = (tid % TPV) * 4;
    const int vlo = (tid / TPV) * VCH;

    ull dw01[SP], dw23[SP];
#pragma unroll
    for (int s = 0; s < SP; ++s) {
        dw01[s] = pack2(__ldg(&dw[(size_t)(cq + 0) * SP + s]),
                        __ldg(&dw[(size_t)(cq + 1) * SP + s]));
        dw23[s] = pack2(__ldg(&dw[(size_t)(cq + 2) * SP + s]),
                        __ldg(&dw[(size_t)(cq + 3) * SP + s]));
    }
    const float* xb = x + ((size_t)b * N) * Ci + cq;
    const size_t ybase = ((size_t)b * N + n0) * Ci + cq;
#pragma unroll 2
    for (int v = vlo; v < vlo + VCH; ++v) {
        const int* iv = idx_s + v * SP;
        ull a01 = 0ull, a23 = 0ull;
#pragma unroll
        for (int s = 0; s < SP; ++s) {
            float4 xv = *reinterpret_cast<const float4*>(
                xb + (size_t)iv[s] * Ci);
            fma2(a01, pack2(xv.x, xv.y), dw01[s]);
            fma2(a23, pack2(xv.z, xv.w), dw23[s]);
        }
        float2 r01 = unpk(a01), r23 = unpk(a23);
        uint2 hv, lv;
        split2(r01.x, r01.y, hv.x, lv.x);
        split2(r23.x, r23.y, hv.y, lv.y);
        *reinterpret_cast<uint2*>(yh + ybase + (size_t)v * Ci) = hv;
        *reinterpret_cast<uint2*>(yl + ybase + (size_t)v * Ci) = lv;
    }
}

// ---------------- bf16x2-split tensor GEMM: C = relu(A @ Bw) ---------------
// 256 thr = 8 warps (4M x 2N); TM=128; m16n8k16 bf16 mma via ldmatrix.
// 3 terms: Ah*Bh + Ah*Bl + Al*Bh (fp32 accum), err ~2^-18.
template <int K, int TN>
__global__ void __launch_bounds__(256, 2)
k_gemm_bf16(const bf16* __restrict__ Ah, const bf16* __restrict__ Al,
            const bf16* __restrict__ Bh, const bf16* __restrict__ Bl,
            float* __restrict__ C, int Co)
{
    constexpr int TM = 128;
    constexpr int KK = 32;
    constexpr int NC = K / KK;
    constexpr int AST = KK + 8;          // bf16 units; 80B rows (odd 16B units)
    constexpr int BST = TN + 8;
    constexpr int NTW = TN / 16;         // 8-col n-tiles per warp
    constexpr int AFq = TM * KK / (8 * 256);   // uint4 per thread per plane (2)
    constexpr int BFq = KK * TN / (8 * 256);   // (2 or 1)

    __shared__ bf16 Ah_s[TM * AST], Al_s[TM * AST];
    __shared__ bf16 Bh_s[KK * BST], Bl_s[KK * BST];

    const int tid = threadIdx.x;
    const int lane = tid & 31;
    const int w = tid >> 5;
    const int wm = w >> 1;
    const int wn = w & 1;
    const int m0 = blockIdx.x * TM;
    const int n0 = blockIdx.y * TN;

    uint4 arh[AFq], arl[AFq], brh[BFq], brl[BFq];

    auto loadAB = [&](int kk) {
#pragma unroll
        for (int i = 0; i < AFq; ++i) {
            const int id = tid + i * 256;
            const int m = id >> 2, q = id & 3;       // KK/8 = 4 chunks per row
            const size_t off = (size_t)(m0 + m) * K + kk + q * 8;
            arh[i] = *reinterpret_cast<const uint4*>(Ah + off);
            arl[i] = *reinterpret_cast<const uint4*>(Al + off);
        }
#pragma unroll
        for (int i = 0; i < BFq; ++i) {
            const int id = tid + i * 256;
            const int r = id / (TN / 8), nq = id % (TN / 8);
            const size_t off = (size_t)(kk + r) * Co + n0 + nq * 8;
            brh[i] = *reinterpret_cast<const uint4*>(Bh + off);
            brl[i] = *reinterpret_cast<const uint4*>(Bl + off);
        }
    };
    auto storeAB = [&]() {
#pragma unroll
        for (int i = 0; i < AFq; ++i) {
            const int id = tid + i * 256;
            const int m = id >> 2, q = id & 3;
            *reinterpret_cast<uint4*>(&Ah_s[m * AST + q * 8]) = arh[i];
            *reinterpret_cast<uint4*>(&Al_s[m * AST + q * 8]) = arl[i];
        }
#pragma unroll
        for (int i = 0; i < BFq; ++i) {
            const int id = tid + i * 256;
            const int r = id / (TN / 8), nq = id % (TN / 8);
            *reinterpret_cast<uint4*>(&Bh_s[r * BST + nq * 8]) = brh[i];
            *reinterpret_cast<uint4*>(&Bl_s[r * BST + nq * 8]) = brl[i];
        }
    };

    float4 acc[2][NTW];
#pragma unroll
    for (int mt = 0; mt < 2; ++mt)
#pragma unroll
        for (int nt = 0; nt < NTW; ++nt)
            acc[mt][nt] = make_float4(0.f, 0.f, 0.f, 0.f);

    const int g = lane >> 3, rr = lane & 7;
    const int lk = lane & 3, lr = lane >> 2;

    loadAB(0);
    for (int c = 0; c < NC; ++c) {
        __syncthreads();
        storeAB();
        __syncthreads();
        if (c + 1 < NC) loadAB((c + 1) * KK);
#pragma unroll
        for (int ks = 0; ks < KK; ks += 16) {
            unsigned ah[2][4], al[2][4];
#pragma unroll
            for (int mt = 0; mt < 2; ++mt) {
                const int row = wm * 32 + mt * 16 + (g & 1) * 8 + rr;
                const int col = ks + (g >> 1) * 8;
                ldsm4(ah[mt], &Ah_s[row * AST + col]);
                ldsm4(al[mt], &Al_s[row * AST + col]);
            }
#pragma unroll
            for (int p = 0; p < NTW / 2; ++p) {
                unsigned bh[4], bl[4];
                const int krow = ks + (g & 1) * 8 + rr;
                const int ncol = wn * (TN / 2) + p * 16 + (g >> 1) * 8;
                ldsm4t(bh, &Bh_s[krow * BST + ncol]);
                ldsm4t(bl, &Bl_s[krow * BST + ncol]);
#pragma unroll
                for (int mt = 0; mt < 2; ++mt) {
                    mma_bf16(acc[mt][2 * p], ah[mt], bh);
                    mma_bf16(acc[mt][2 * p], ah[mt], bl);
                    mma_bf16(acc[mt][2 * p], al[mt], bh);
                    mma_bf16(acc[mt][2 * p + 1], ah[mt], bh + 2);
                    mma_bf16(acc[mt][2 * p + 1], ah[mt], bl + 2);
                    mma_bf16(acc[mt][2 * p + 1], al[mt], bh + 2);
                }
            }
        }
    }

#pragma unroll
    for (int mt = 0; mt < 2; ++mt) {
        const int row = m0 + wm * 32 + mt * 16 + lr;
#pragma unroll
        for (int nt = 0; nt < NTW; ++nt) {
            const int colg = n0 + wn * (TN / 2) + nt * 8 + 2 * lk;
            float2 o0 = make_float2(fmaxf(acc[mt][nt].x, 0.f),
                                    fmaxf(acc[mt][nt].y, 0.f));
            float2 o1 = make_float2(fmaxf(acc[mt][nt].z, 0.f),
                                    fmaxf(acc[mt][nt].w, 0.f));
            *reinterpret_cast<float2*>(C + (size_t)row * Co + colg) = o0;
            *reinterpret_cast<float2*>(C + (size_t)(row + 8) * Co + colg) = o1;
        }
    }
}

// ---------------- head: Ci=64 -> Co=3, no relu -----------------------------
__global__ void __launch_bounds__(256)
k_head(const float* __restrict__ x, const int* __restrict__ idx,
       const float* __restrict__ dw, const float* __restrict__ pw,
       float* __restrict__ out, int N)
{
    constexpr int Ci = 64;
    constexpr int VT = 32;
    __shared__ float y_s[VT][Ci];
    __shared__ float pw_s[Ci * 3];
    __shared__ int idx_s[VT * SP];
    const int b = blockIdx.y, n0 = blockIdx.x * VT, tid = threadIdx.x;

    if (tid < Ci * 3) pw_s[tid] = pw[tid];
    for (int t = tid; t < VT * SP; t += 256)
        idx_s[t] = idx[(size_t)n0 * SP + t];
    __syncthreads();

    {
        const int ci = tid & (Ci - 1);
        const int vlo = (tid / Ci) * (VT / 4);
        float dwr[SP];
#pragma unroll
        for (int s = 0; s < SP; ++s) dwr[s] = __ldg(&dw[(size_t)ci * SP + s]);
        const float* xb = x + ((size_t)b * N) * Ci + ci;
#pragma unroll 2
        for (int v = vlo; v < vlo + VT / 4; ++v) {
            float acc = 0.f;
#pragma unroll
            for (int s = 0; s < SP; ++s)
                acc = fmaf(xb[(size_t)idx_s[v * SP + s] * Ci], dwr[s], acc);
            y_s[v][ci] = acc;
        }
    }
    __syncthreads();

    if (tid < VT * 3) {
        const int v = tid / 3, co = tid % 3;
        float acc = 0.f;
#pragma unroll
        for (int ci = 0; ci < Ci; ++ci)
            acc = fmaf(y_s[v][ci], pw_s[ci * 3 + co], acc);
        out[((size_t)b * N + n0 + v) * 3 + co] = acc;
    }
}

// ---------------------------------------------------------------------------
extern "C" void kernel_launch(void* const* d_in, const int* in_sizes, int n_in,
                              void* d_out, int out_size)
{
    const float* uv   = (const float*)d_in[0];
    const float* feat = (const float*)d_in[1];
    const float* up   = (const float*)d_in[2];
    const float* dw0  = (const float*)d_in[3];
    const float* pw0  = (const float*)d_in[4];
    const float* dw1  = (const float*)d_in[5];
    const float* pw1  = (const float*)d_in[6];
    const float* dw2  = (const float*)d_in[7];
    const float* pw2  = (const float*)d_in[8];
    const float* dw3  = (const float*)d_in[9];
    const float* pw3  = (const float*)d_in[10];
    const float* dwh  = (const float*)d_in[11];
    const float* pwh  = (const float*)d_in[12];

    // Resolve input ordering ambiguity via element counts.
    const float *upv0, *upv1, *upv2, *upv3;
    const int *spi0, *spi1, *spi2, *spi3, *upc0, *upc1, *upc2, *upc3;
    if (in_sizes[13] == 37632) {
        upv0 = (const float*)d_in[13]; upv1 = (const float*)d_in[14];
        upv2 = (const float*)d_in[15]; upv3 = (const float*)d_in[16];
        spi0 = (const int*)d_in[17]; spi1 = (const int*)d_in[18];
        spi2 = (const int*)d_in[19]; spi3 = (const int*)d_in[20];
        upc0 = (const int*)d_in[21]; upc1 = (const int*)d_in[22];
        upc2 = (const int*)d_in[23]; upc3 = (const int*)d_in[24];
    } else {
        spi0 = (const int*)d_in[13]; upc0 = (const int*)d_in[14]; upv0 = (const float*)d_in[15];
        spi1 = (const int*)d_in[16]; upc1 = (const int*)d_in[17]; upv1 = (const float*)d_in[18];
        spi2 = (const int*)d_in[19]; upc2 = (const int*)d_in[20]; upv2 = (const float*)d_in[21];
        spi3 = (const int*)d_in[22]; upc3 = (const int*)d_in[23]; upv3 = (const float*)d_in[24];
    }

    float *gsP, *bufA, *bufB, *bufC;
    bf16 *pwhP, *pwlP;
    cudaGetSymbolAddress((void**)&gsP, g_gs);
    cudaGetSymbolAddress((void**)&bufA, g_bufA);
    cudaGetSymbolAddress((void**)&bufB, g_bufB);
    cudaGetSymbolAddress((void**)&bufC, g_bufC);
    cudaGetSymbolAddress((void**)&pwhP, g_pwh);
    cudaGetSymbolAddress((void**)&pwlP, g_pwl);
    float* outp = (float*)d_out;

    // pw split plane offsets (elements)
    const int O0 = 0, O1 = 65536, O2 = 131072, O3 = 163840;
    k_splitw<<<256, 256>>>(pw0, pwhP + O0, pwlP + O0, 65536);
    k_splitw<<<256, 256>>>(pw1, pwhP + O1, pwlP + O1, 65536);
    k_splitw<<<128, 256>>>(pw2, pwhP + O2, pwlP + O2, 32768);
    k_splitw<<<32, 256>>>(pw3, pwhP + O3, pwlP + O3, 8192);

    // 1) grid sample; 2) upsample -> bufB (b,784,256)
    k_gridsample<<<B, 256>>>(uv, feat, gsP);
    k_upsample<<<dim3(49, B), 256>>>(up, gsP, bufB);

    bf16* yH = (bf16*)bufC;

    // stage 0: pool 784->1568, gather idx_3 (split), GEMM 256->256
    {
        bf16* yL = yH + (size_t)B * 1568 * 256;
        k_pool<256><<<dim3(1568 / 4, B), 256>>>((const float4*)bufB, upc3, upv3,
                                                (float4*)bufA, 784, 1568);
        k_gather<256><<<dim3(1568 / 32, B), 256>>>(bufA, spi3, dw0, yH, yL, 1568);
        k_gemm_bf16<256, 128><<<dim3(B * 1568 / 128, 2), 256>>>(
            yH, yL, pwhP + O0, pwlP + O0, bufB, 256);
    }
    // stage 1: pool 1568->3136, gather idx_2, GEMM 256->256
    {
        bf16* yL = yH + (size_t)B * 3136 * 256;
        k_pool<256><<<dim3(3136 / 4, B), 256>>>((const float4*)bufB, upc2, upv2,
                                                (float4*)bufA, 1568, 3136);
        k_gather<256><<<dim3(3136 / 32, B), 256>>>(bufA, spi2, dw1, yH, yL, 3136);
        k_gemm_bf16<256, 128><<<dim3(B * 3136 / 128, 2), 256>>>(
            yH, yL, pwhP + O1, pwlP + O1, bufB, 256);
    }
    // stage 2: pool 3136->6272, gather idx_1, GEMM 256->128
    {
        bf16* yL = yH + (size_t)B * 6272 * 256;
        k_pool<256><<<dim3(6272 / 4, B), 256>>>((const float4*)bufB, upc1, upv1,
                                                (float4*)bufA, 3136, 6272);
        k_gather<256><<<dim3(6272 / 32, B), 256>>>(bufA, spi1, dw2, yH, yL, 6272);
        k_gemm_bf16<256, 128><<<dim3(B * 6272 / 128, 1), 256>>>(
            yH, yL, pwhP + O2, pwlP + O2, bufB, 128);
    }
    // stage 3: pool 6272->12544 (Ci=128), gather idx_0, GEMM 128->64
    {
        bf16* yL = yH + (size_t)B * 12544 * 128;
        k_pool<128><<<dim3(12544 / 8, B), 256>>>((const float4*)bufB, upc0, upv0,
                                                 (float4*)bufA, 6272, 12544);
        k_gather<128><<<dim3(12544 / 32, B), 256>>>(bufA, spi0, dw3, yH, yL, 12544);
        k_gemm_bf16<128, 64><<<dim3(B * 12544 / 128, 1), 256>>>(
            yH, yL, pwhP + O3, pwlP + O3, bufB, 64);
    }

    // head: Ci=64 -> 3, no relu
    k_head<<<dim3(12544 / 32, B), 256>>>(bufB, spi0, dwh, pwh, outp, 12544);
}

// round 10
// speedup vs baseline: 1.3487x; 1.0446x over previous
#include <cuda_runtime.h>
#include <cuda_bf16.h>
#include <cstddef>

// ---------------------------------------------------------------------------
// DWReg2DDecode3D: grid_sample -> upsample GEMM -> 4x(pool -> spiral gather
// (bf16x2-split output) -> bf16 tensor GEMM+relu) -> head dsconv.  B=16,SP=9.
// ---------------------------------------------------------------------------

#define B 16
#define SP 9

typedef unsigned long long ull;
typedef __nv_bfloat16 bf16;

// scratch (device globals; no allocations allowed)
__device__ float g_gs[B * 64 * 256];          // grid-sampled feats
__device__ float g_bufB[12845056];            // conv outputs   (max 16*3136*256)
__device__ float g_bufA[25690112];            // pool outputs   (max 16*12544*128)
__device__ float g_bufC[25690112];            // gathered y, 2 bf16 planes
__device__ bf16  g_pwh[172032];               // pre-split pw high planes
__device__ bf16  g_pwl[172032];               // pre-split pw low planes

// ---------------- packed f32x2 helpers (sm_10x FFMA2 path) -----------------
__device__ __forceinline__ void fma2(ull& d, ull a, ull b) {
    asm("fma.rn.f32x2 %0, %1, %2, %0;" : "+l"(d) : "l"(a), "l"(b));
}
__device__ __forceinline__ ull pack2(float a, float b) {
    ull u;
    asm("mov.b64 %0, {%1, %2};" : "=l"(u) : "f"(a), "f"(b));
    return u;
}
__device__ __forceinline__ float2 unpk(ull u) {
    float2 r;
    asm("mov.b64 {%0, %1}, %2;" : "=f"(r.x), "=f"(r.y) : "l"(u));
    return r;
}

// ---------------- bf16 mma helpers -----------------------------------------
__device__ __forceinline__ void mma_bf16(float4& c, const unsigned* a,
                                         const unsigned* b) {
    asm("mma.sync.aligned.m16n8k16.row.col.f32.bf16.bf16.f32 "
        "{%0,%1,%2,%3}, {%4,%5,%6,%7}, {%8,%9}, {%0,%1,%2,%3};"
        : "+f"(c.x), "+f"(c.y), "+f"(c.z), "+f"(c.w)
        : "r"(a[0]), "r"(a[1]), "r"(a[2]), "r"(a[3]), "r"(b[0]), "r"(b[1]));
}
__device__ __forceinline__ void ldsm4(unsigned* r, const bf16* p) {
    unsigned a = (unsigned)__cvta_generic_to_shared(p);
    asm volatile("ldmatrix.sync.aligned.m8n8.x4.shared.b16 {%0,%1,%2,%3}, [%4];"
                 : "=r"(r[0]), "=r"(r[1]), "=r"(r[2]), "=r"(r[3]) : "r"(a));
}
__device__ __forceinline__ void ldsm4t(unsigned* r, const bf16* p) {
    unsigned a = (unsigned)__cvta_generic_to_shared(p);
    asm volatile("ldmatrix.sync.aligned.m8n8.x4.trans.shared.b16 {%0,%1,%2,%3}, [%4];"
                 : "=r"(r[0]), "=r"(r[1]), "=r"(r[2]), "=r"(r[3]) : "r"(a));
}
// split v -> (bf16 hi, bf16 lo) pair-packed words
__device__ __forceinline__ void split2(float a, float b, unsigned& h, unsigned& l) {
    bf16 ha = __float2bfloat16(a), hb = __float2bfloat16(b);
    bf16 la = __float2bfloat16(a - __bfloat162float(ha));
    bf16 lb = __float2bfloat16(b - __bfloat162float(hb));
    __nv_bfloat162 hh = __halves2bfloat162(ha, hb);
    __nv_bfloat162 ll = __halves2bfloat162(la, lb);
    h = *reinterpret_cast<unsigned*>(&hh);
    l = *reinterpret_cast<unsigned*>(&ll);
}

// ---------------- grid sample (bilinear, align_corners, zero pad) ----------
__global__ void __launch_bounds__(256)
k_gridsample(const float* __restrict__ uv, const float* __restrict__ feat,
             float* __restrict__ gs)
{
    const int b = blockIdx.x, c = threadIdx.x;
    const float* fb = feat + ((size_t)b * 256 + c) * 16;
    for (int p = 0; p < 64; ++p) {
        float gx = (uv[((size_t)b * 64 + p) * 2 + 0] - 0.5f) * 2.f;
        float gy = (uv[((size_t)b * 64 + p) * 2 + 1] - 0.5f) * 2.f;
        gx = fminf(fmaxf(gx, -1.f), 1.f);
        gy = fminf(fmaxf(gy, -1.f), 1.f);
        float x = (gx + 1.f) * 0.5f * 3.f;
        float y = (gy + 1.f) * 0.5f * 3.f;
        float x0f = floorf(x), y0f = floorf(y);
        int x0 = (int)x0f, y0 = (int)y0f;
        int x1 = x0 + 1, y1 = y0 + 1;
        float fx = x - x0f, fy = y - y0f;
        float wa = (1.f - fx) * (1.f - fy);
        float wb = (1.f - fx) * fy;
        float wc = fx * (1.f - fy);
        float wd = fx * fy;
        float Ia = (x0 >= 0 && x0 < 4 && y0 >= 0 && y0 < 4) ? fb[y0 * 4 + x0] : 0.f;
        float Ib = (x0 >= 0 && x0 < 4 && y1 >= 0 && y1 < 4) ? fb[y1 * 4 + x0] : 0.f;
        float Ic = (x1 >= 0 && x1 < 4 && y0 >= 0 && y0 < 4) ? fb[y0 * 4 + x1] : 0.f;
        float Id = (x1 >= 0 && x1 < 4 && y1 >= 0 && y1 < 4) ? fb[y1 * 4 + x1] : 0.f;
        gs[((size_t)b * 64 + p) * 256 + c] = Ia * wa + Ib * wb + Ic * wc + Id * wd;
    }
}

// ---------------- upsample GEMM: out[b,v,c] = sum_p up[v,p]*gs[b,p,c] ------
__global__ void __launch_bounds__(256)
k_upsample(const float* __restrict__ up, const float* __restrict__ gs,
           float* __restrict__ out)
{
    constexpr int VT = 16;
    __shared__ float up_s[VT][64];
    const int b = blockIdx.y, v0 = blockIdx.x * VT, c = threadIdx.x;
    for (int t = threadIdx.x; t < VT * 64; t += 256)
        up_s[t / 64][t % 64] = up[(size_t)(v0 + t / 64) * 64 + (t % 64)];
    __syncthreads();
    float acc[VT];
#pragma unroll
    for (int i = 0; i < VT; ++i) acc[i] = 0.f;
    for (int p = 0; p < 64; ++p) {
        float g = gs[((size_t)b * 64 + p) * 256 + c];
#pragma unroll
        for (int i = 0; i < VT; ++i) acc[i] = fmaf(up_s[i][p], g, acc[i]);
    }
#pragma unroll
    for (int i = 0; i < VT; ++i)
        out[((size_t)b * 784 + v0 + i) * 256 + c] = acc[i];
}

// ---------------- mesh up-pool ---------------------------------------------
template <int Ci>
__global__ void __launch_bounds__(256)
k_pool(const float4* __restrict__ x, const int* __restrict__ col,
       const float* __restrict__ val, float4* __restrict__ out,
       int Nin, int Nout)
{
    constexpr int CQ = Ci / 4;
    constexpr int VPB = 256 / CQ;
    const int b = blockIdx.y;
    const int n = blockIdx.x * VPB + threadIdx.x / CQ;
    const int cq = threadIdx.x % CQ;
    if (n >= Nout) return;
    const int c0 = col[3 * n + 0], c1 = col[3 * n + 1], c2 = col[3 * n + 2];
    const float v0 = val[3 * n + 0], v1 = val[3 * n + 1], v2 = val[3 * n + 2];
    const float4* xb = x + (size_t)b * Nin * CQ;
    float4 a = xb[(size_t)c0 * CQ + cq];
    float4 bb = xb[(size_t)c1 * CQ + cq];
    float4 cc = xb[(size_t)c2 * CQ + cq];
    float4 r;
    r.x = a.x * v0 + bb.x * v1 + cc.x * v2;
    r.y = a.y * v0 + bb.y * v1 + cc.y * v2;
    r.z = a.z * v0 + bb.z * v1 + cc.z * v2;
    r.w = a.w * v0 + bb.w * v1 + cc.w * v2;
    out[((size_t)b * Nout + n) * CQ + cq] = r;
}

// ---------------- fused pw pre-split: all 4 weights in one launch ----------
__global__ void __launch_bounds__(256)
k_splitw4(const float* __restrict__ w0, const float* __restrict__ w1,
          const float* __restrict__ w2, const float* __restrict__ w3,
          bf16* __restrict__ h, bf16* __restrict__ l)
{
    const int i = blockIdx.x * 256 + threadIdx.x;
    if (i >= 172032) return;
    float v;
    if (i < 65536)       v = w0[i];
    else if (i < 131072) v = w1[i - 65536];
    else if (i < 163840) v = w2[i - 131072];
    else                 v = w3[i - 163840];
    bf16 hh = __float2bfloat16(v);
    h[i] = hh;
    l[i] = __float2bfloat16(v - __bfloat162float(hh));
}

// ---------------- spiral gather + depthwise -> bf16x2 split planes ---------
template <int Ci>
__global__ void __launch_bounds__(256)
k_gather(const float* __restrict__ x, const int* __restrict__ idx,
         const float* __restrict__ dw, bf16* __restrict__ yh,
         bf16* __restrict__ yl, int N)
{
    constexpr int VT = 32;
    constexpr int TPV = Ci / 4;
    constexpr int VG = 256 / TPV;
    constexpr int VCH = VT / VG;
    __shared__ int idx_s[VT * SP];
    const int b = blockIdx.y;
    const int n0 = blockIdx.x * VT;
    const int tid = threadIdx.x;

    for (int t = tid; t < VT * SP; t += 256)
        idx_s[t] = idx[(size_t)n0 * SP + t];
    __syncthreads();

    const int cq = (tid % TPV) * 4;
    const int vlo = (tid / TPV) * VCH;

    ull dw01[SP], dw23[SP];
#pragma unroll
    for (int s = 0; s < SP; ++s) {
        dw01[s] = pack2(__ldg(&dw[(size_t)(cq + 0) * SP + s]),
                        __ldg(&dw[(size_t)(cq + 1) * SP + s]));
        dw23[s] = pack2(__ldg(&dw[(size_t)(cq + 2) * SP + s]),
                        __ldg(&dw[(size_t)(cq + 3) * SP + s]));
    }
    const float* xb = x + ((size_t)b * N) * Ci + cq;
    const size_t ybase = ((size_t)b * N + n0) * Ci + cq;
#pragma unroll 2
    for (int v = vlo; v < vlo + VCH; ++v) {
        const int* iv = idx_s + v * SP;
        ull a01 = 0ull, a23 = 0ull;
#pragma unroll
        for (int s = 0; s < SP; ++s) {
            float4 xv = *reinterpret_cast<const float4*>(
                xb + (size_t)iv[s] * Ci);
            fma2(a01, pack2(xv.x, xv.y), dw01[s]);
            fma2(a23, pack2(xv.z, xv.w), dw23[s]);
        }
        float2 r01 = unpk(a01), r23 = unpk(a23);
        uint2 hv, lv;
        split2(r01.x, r01.y, hv.x, lv.x);
        split2(r23.x, r23.y, hv.y, lv.y);
        *reinterpret_cast<uint2*>(yh + ybase + (size_t)v * Ci) = hv;
        *reinterpret_cast<uint2*>(yl + ybase + (size_t)v * Ci) = lv;
    }
}

// ---------------- bf16x2-split tensor GEMM: C = relu(A @ Bw) ---------------
// 256 thr = 8 warps (4M x 2N); TM=128; m16n8k16 bf16 mma via ldmatrix.
// 3 terms: Ah*Bh + Ah*Bl + Al*Bh (fp32 accum), err ~2^-18.
template <int K, int TN>
__global__ void __launch_bounds__(256, 2)
k_gemm_bf16(const bf16* __restrict__ Ah, const bf16* __restrict__ Al,
            const bf16* __restrict__ Bh, const bf16* __restrict__ Bl,
            float* __restrict__ C, int Co)
{
    constexpr int TM = 128;
    constexpr int KK = 32;
    constexpr int NC = K / KK;
    constexpr int AST = KK + 8;
    constexpr int BST = TN + 8;
    constexpr int NTW = TN / 16;
    constexpr int AFq = TM * KK / (8 * 256);
    constexpr int BFq = KK * TN / (8 * 256);

    __shared__ bf16 Ah_s[TM * AST], Al_s[TM * AST];
    __shared__ bf16 Bh_s[KK * BST], Bl_s[KK * BST];

    const int tid = threadIdx.x;
    const int lane = tid & 31;
    const int w = tid >> 5;
    const int wm = w >> 1;
    const int wn = w & 1;
    const int m0 = blockIdx.x * TM;
    const int n0 = blockIdx.y * TN;

    uint4 arh[AFq], arl[AFq], brh[BFq], brl[BFq];

    auto loadAB = [&](int kk) {
#pragma unroll
        for (int i = 0; i < AFq; ++i) {
            const int id = tid + i * 256;
            const int m = id >> 2, q = id & 3;
            const size_t off = (size_t)(m0 + m) * K + kk + q * 8;
            arh[i] = *reinterpret_cast<const uint4*>(Ah + off);
            arl[i] = *reinterpret_cast<const uint4*>(Al + off);
        }
#pragma unroll
        for (int i = 0; i < BFq; ++i) {
            const int id = tid + i * 256;
            const int r = id / (TN / 8), nq = id % (TN / 8);
            const size_t off = (size_t)(kk + r) * Co + n0 + nq * 8;
            brh[i] = *reinterpret_cast<const uint4*>(Bh + off);
            brl[i] = *reinterpret_cast<const uint4*>(Bl + off);
        }
    };
    auto storeAB = [&]() {
#pragma unroll
        for (int i = 0; i < AFq; ++i) {
            const int id = tid + i * 256;
            const int m = id >> 2, q = id & 3;
            *reinterpret_cast<uint4*>(&Ah_s[m * AST + q * 8]) = arh[i];
            *reinterpret_cast<uint4*>(&Al_s[m * AST + q * 8]) = arl[i];
        }
#pragma unroll
        for (int i = 0; i < BFq; ++i) {
            const int id = tid + i * 256;
            const int r = id / (TN / 8), nq = id % (TN / 8);
            *reinterpret_cast<uint4*>(&Bh_s[r * BST + nq * 8]) = brh[i];
            *reinterpret_cast<uint4*>(&Bl_s[r * BST + nq * 8]) = brl[i];
        }
    };

    float4 acc[2][NTW];
#pragma unroll
    for (int mt = 0; mt < 2; ++mt)
#pragma unroll
        for (int nt = 0; nt < NTW; ++nt)
            acc[mt][nt] = make_float4(0.f, 0.f, 0.f, 0.f);

    const int g = lane >> 3, rr = lane & 7;
    const int lk = lane & 3, lr = lane >> 2;

    loadAB(0);
    for (int c = 0; c < NC; ++c) {
        __syncthreads();
        storeAB();
        __syncthreads();
        if (c + 1 < NC) loadAB((c + 1) * KK);
#pragma unroll
        for (int ks = 0; ks < KK; ks += 16) {
            unsigned ah[2][4], al[2][4];
#pragma unroll
            for (int mt = 0; mt < 2; ++mt) {
                const int row = wm * 32 + mt * 16 + (g & 1) * 8 + rr;
                const int col = ks + (g >> 1) * 8;
                ldsm4(ah[mt], &Ah_s[row * AST + col]);
                ldsm4(al[mt], &Al_s[row * AST + col]);
            }
#pragma unroll
            for (int p = 0; p < NTW / 2; ++p) {
                unsigned bh[4], bl[4];
                const int krow = ks + (g & 1) * 8 + rr;
                const int ncol = wn * (TN / 2) + p * 16 + (g >> 1) * 8;
                ldsm4t(bh, &Bh_s[krow * BST + ncol]);
                ldsm4t(bl, &Bl_s[krow * BST + ncol]);
#pragma unroll
                for (int mt = 0; mt < 2; ++mt) {
                    mma_bf16(acc[mt][2 * p], ah[mt], bh);
                    mma_bf16(acc[mt][2 * p], ah[mt], bl);
                    mma_bf16(acc[mt][2 * p], al[mt], bh);
                    mma_bf16(acc[mt][2 * p + 1], ah[mt], bh + 2);
                    mma_bf16(acc[mt][2 * p + 1], ah[mt], bl + 2);
                    mma_bf16(acc[mt][2 * p + 1], al[mt], bh + 2);
                }
            }
        }
    }

#pragma unroll
    for (int mt = 0; mt < 2; ++mt) {
        const int row = m0 + wm * 32 + mt * 16 + lr;
#pragma unroll
        for (int nt = 0; nt < NTW; ++nt) {
            const int colg = n0 + wn * (TN / 2) + nt * 8 + 2 * lk;
            float2 o0 = make_float2(fmaxf(acc[mt][nt].x, 0.f),
                                    fmaxf(acc[mt][nt].y, 0.f));
            float2 o1 = make_float2(fmaxf(acc[mt][nt].z, 0.f),
                                    fmaxf(acc[mt][nt].w, 0.f));
            *reinterpret_cast<float2*>(C + (size_t)row * Co + colg) = o0;
            *reinterpret_cast<float2*>(C + (size_t)(row + 8) * Co + colg) = o1;
        }
    }
}

// ---------------- head: Ci=64 -> Co=3, float4 gathers ----------------------
// y_s row stride Ci+4 = 68 floats = 272 B (16B-aligned for float4 stores).
__global__ void __launch_bounds__(256)
k_head(const float* __restrict__ x, const int* __restrict__ idx,
       const float* __restrict__ dw, const float* __restrict__ pw,
       float* __restrict__ out, int N)
{
    constexpr int Ci = 64;
    constexpr int VT = 64;
    constexpr int TPV = Ci / 4;          // 16 threads per vertex
    constexpr int VG = 256 / TPV;        // 16 concurrent vertices
    constexpr int VCH = VT / VG;         // 4 vertices per thread
    __shared__ __align__(16) float y_s[VT][Ci + 4];
    __shared__ float pw_s[Ci * 3];
    __shared__ int idx_s[VT * SP];
    const int b = blockIdx.y, n0 = blockIdx.x * VT, tid = threadIdx.x;

    if (tid < Ci * 3) pw_s[tid] = pw[tid];
    for (int t = tid; t < VT * SP; t += 256)
        idx_s[t] = idx[(size_t)n0 * SP + t];
    __syncthreads();

    {
        const int cq = (tid % TPV) * 4;
        const int vlo = (tid / TPV) * VCH;
        ull dw01[SP], dw23[SP];
#pragma unroll
        for (int s = 0; s < SP; ++s) {
            dw01[s] = pack2(__ldg(&dw[(size_t)(cq + 0) * SP + s]),
                            __ldg(&dw[(size_t)(cq + 1) * SP + s]));
            dw23[s] = pack2(__ldg(&dw[(size_t)(cq + 2) * SP + s]),
                            __ldg(&dw[(size_t)(cq + 3) * SP + s]));
        }
        const float* xb = x + ((size_t)b * N) * Ci + cq;
#pragma unroll 2
        for (int v = vlo; v < vlo + VCH; ++v) {
            const int* iv = idx_s + v * SP;
            ull a01 = 0ull, a23 = 0ull;
#pragma unroll
            for (int s = 0; s < SP; ++s) {
                float4 xv = *reinterpret_cast<const float4*>(
                    xb + (size_t)iv[s] * Ci);
                fma2(a01, pack2(xv.x, xv.y), dw01[s]);
                fma2(a23, pack2(xv.z, xv.w), dw23[s]);
            }
            float2 r01 = unpk(a01), r23 = unpk(a23);
            *reinterpret_cast<float4*>(&y_s[v][cq]) =
                make_float4(r01.x, r01.y, r23.x, r23.y);
        }
    }
    __syncthreads();

    if (tid < VT * 3) {
        const int v = tid / 3, co = tid % 3;
        float acc = 0.f;
#pragma unroll
        for (int ci = 0; ci < Ci; ++ci)
            acc = fmaf(y_s[v][ci], pw_s[ci * 3 + co], acc);
        out[((size_t)b * N + n0 + v) * 3 + co] = acc;
    }
}

// ---------------------------------------------------------------------------
extern "C" void kernel_launch(void* const* d_in, const int* in_sizes, int n_in,
                              void* d_out, int out_size)
{
    const float* uv   = (const float*)d_in[0];
    const float* feat = (const float*)d_in[1];
    const float* up   = (const float*)d_in[2];
    const float* dw0  = (const float*)d_in[3];
    const float* pw0  = (const float*)d_in[4];
    const float* dw1  = (const float*)d_in[5];
    const float* pw1  = (const float*)d_in[6];
    const float* dw2  = (const float*)d_in[7];
    const float* pw2  = (const float*)d_in[8];
    const float* dw3  = (const float*)d_in[9];
    const float* pw3  = (const float*)d_in[10];
    const float* dwh  = (const float*)d_in[11];
    const float* pwh  = (const float*)d_in[12];

    // Resolve input ordering ambiguity via element counts.
    const float *upv0, *upv1, *upv2, *upv3;
    const int *spi0, *spi1, *spi2, *spi3, *upc0, *upc1, *upc2, *upc3;
    if (in_sizes[13] == 37632) {
        upv0 = (const float*)d_in[13]; upv1 = (const float*)d_in[14];
        upv2 = (const float*)d_in[15]; upv3 = (const float*)d_in[16];
        spi0 = (const int*)d_in[17]; spi1 = (const int*)d_in[18];
        spi2 = (const int*)d_in[19]; spi3 = (const int*)d_in[20];
        upc0 = (const int*)d_in[21]; upc1 = (const int*)d_in[22];
        upc2 = (const int*)d_in[23]; upc3 = (const int*)d_in[24];
    } else {
        spi0 = (const int*)d_in[13]; upc0 = (const int*)d_in[14]; upv0 = (const float*)d_in[15];
        spi1 = (const int*)d_in[16]; upc1 = (const int*)d_in[17]; upv1 = (const float*)d_in[18];
        spi2 = (const int*)d_in[19]; upc2 = (const int*)d_in[20]; upv2 = (const float*)d_in[21];
        spi3 = (const int*)d_in[22]; upc3 = (const int*)d_in[23]; upv3 = (const float*)d_in[24];
    }

    float *gsP, *bufA, *bufB, *bufC;
    bf16 *pwhP, *pwlP;
    cudaGetSymbolAddress((void**)&gsP, g_gs);
    cudaGetSymbolAddress((void**)&bufA, g_bufA);
    cudaGetSymbolAddress((void**)&bufB, g_bufB);
    cudaGetSymbolAddress((void**)&bufC, g_bufC);
    cudaGetSymbolAddress((void**)&pwhP, g_pwh);
    cudaGetSymbolAddress((void**)&pwlP, g_pwl);
    float* outp = (float*)d_out;

    // pw split plane offsets (elements)
    const int O0 = 0, O1 = 65536, O2 = 131072, O3 = 163840;
    k_splitw4<<<672, 256>>>(pw0, pw1, pw2, pw3, pwhP, pwlP);

    // 1) grid sample; 2) upsample -> bufB (b,784,256)
    k_gridsample<<<B, 256>>>(uv, feat, gsP);
    k_upsample<<<dim3(49, B), 256>>>(up, gsP, bufB);

    bf16* yH = (bf16*)bufC;

    // stage 0: pool 784->1568, gather idx_3 (split), GEMM 256->256
    {
        bf16* yL = yH + (size_t)B * 1568 * 256;
        k_pool<256><<<dim3(1568 / 4, B), 256>>>((const float4*)bufB, upc3, upv3,
                                                (float4*)bufA, 784, 1568);
        k_gather<256><<<dim3(1568 / 32, B), 256>>>(bufA, spi3, dw0, yH, yL, 1568);
        k_gemm_bf16<256, 128><<<dim3(B * 1568 / 128, 2), 256>>>(
            yH, yL, pwhP + O0, pwlP + O0, bufB, 256);
    }
    // stage 1: pool 1568->3136, gather idx_2, GEMM 256->256
    {
        bf16* yL = yH + (size_t)B * 3136 * 256;
        k_pool<256><<<dim3(3136 / 4, B), 256>>>((const float4*)bufB, upc2, upv2,
                                                (float4*)bufA, 1568, 3136);
        k_gather<256><<<dim3(3136 / 32, B), 256>>>(bufA, spi2, dw1, yH, yL, 3136);
        k_gemm_bf16<256, 128><<<dim3(B * 3136 / 128, 2), 256>>>(
            yH, yL, pwhP + O1, pwlP + O1, bufB, 256);
    }
    // stage 2: pool 3136->6272, gather idx_1, GEMM 256->128
    {
        bf16* yL = yH + (size_t)B * 6272 * 256;
        k_pool<256><<<dim3(6272 / 4, B), 256>>>((const float4*)bufB, upc1, upv1,
                                                (float4*)bufA, 3136, 6272);
        k_gather<256><<<dim3(6272 / 32, B), 256>>>(bufA, spi1, dw2, yH, yL, 6272);
        k_gemm_bf16<256, 128><<<dim3(B * 6272 / 128, 1), 256>>>(
            yH, yL, pwhP + O2, pwlP + O2, bufB, 128);
    }
    // stage 3: pool 6272->12544 (Ci=128), gather idx_0, GEMM 128->64
    {
        bf16* yL = yH + (size_t)B * 12544 * 128;
        k_pool<128><<<dim3(12544 / 8, B), 256>>>((const float4*)bufB, upc0, upv0,
                                                 (float4*)bufA, 6272, 12544);
        k_gather<128><<<dim3(12544 / 32, B), 256>>>(bufA, spi0, dw3, yH, yL, 12544);
        k_gemm_bf16<128, 64><<<dim3(B * 12544 / 128, 1), 256>>>(
            yH, yL, pwhP + O3, pwlP + O3, bufB, 64);
    }

    // head: Ci=64 -> 3, no relu
    k_head<<<dim3(12544 / 64, B), 256>>>(bufB, spi0, dwh, pwh, outp, 12544);
}

// round 11
// speedup vs baseline: 1.3934x; 1.0332x over previous
#include <cuda_runtime.h>
#include <cuda_bf16.h>
#include <cstddef>

// ---------------------------------------------------------------------------
// DWReg2DDecode3D: grid_sample -> upsample GEMM -> 4x(pool -> FUSED spiral
// gather + bf16x2-split tensor GEMM + relu) -> head dsconv.  B=16, SP=9.
// The fused kernel overlaps L2-bound gathers with tensor-pipe MMAs.
// ---------------------------------------------------------------------------

#define B 16
#define SP 9

typedef unsigned long long ull;
typedef __nv_bfloat16 bf16;

// scratch (device globals; no allocations allowed)
__device__ float g_gs[B * 64 * 256];          // grid-sampled feats
__device__ float g_bufB[12845056];            // conv outputs   (max 16*3136*256)
__device__ float g_bufA[25690112];            // pool outputs   (max 16*12544*128)
__device__ bf16  g_pwh[172032];               // pre-split pw high planes
__device__ bf16  g_pwl[172032];               // pre-split pw low planes
__device__ float g_dwt[8064];                 // transposed dw (per stage)

// ---------------- packed f32x2 helpers -------------------------------------
__device__ __forceinline__ void fma2(ull& d, ull a, ull b) {
    asm("fma.rn.f32x2 %0, %1, %2, %0;" : "+l"(d) : "l"(a), "l"(b));
}
__device__ __forceinline__ ull pack2(float a, float b) {
    ull u;
    asm("mov.b64 %0, {%1, %2};" : "=l"(u) : "f"(a), "f"(b));
    return u;
}
__device__ __forceinline__ float2 unpk(ull u) {
    float2 r;
    asm("mov.b64 {%0, %1}, %2;" : "=f"(r.x), "=f"(r.y) : "l"(u));
    return r;
}

// ---------------- bf16 mma helpers -----------------------------------------
__device__ __forceinline__ void mma_bf16(float4& c, const unsigned* a,
                                         const unsigned* b) {
    asm("mma.sync.aligned.m16n8k16.row.col.f32.bf16.bf16.f32 "
        "{%0,%1,%2,%3}, {%4,%5,%6,%7}, {%8,%9}, {%0,%1,%2,%3};"
        : "+f"(c.x), "+f"(c.y), "+f"(c.z), "+f"(c.w)
        : "r"(a[0]), "r"(a[1]), "r"(a[2]), "r"(a[3]), "r"(b[0]), "r"(b[1]));
}
__device__ __forceinline__ void ldsm4(unsigned* r, const bf16* p) {
    unsigned a = (unsigned)__cvta_generic_to_shared(p);
    asm volatile("ldmatrix.sync.aligned.m8n8.x4.shared.b16 {%0,%1,%2,%3}, [%4];"
                 : "=r"(r[0]), "=r"(r[1]), "=r"(r[2]), "=r"(r[3]) : "r"(a));
}
__device__ __forceinline__ void ldsm4t(unsigned* r, const bf16* p) {
    unsigned a = (unsigned)__cvta_generic_to_shared(p);
    asm volatile("ldmatrix.sync.aligned.m8n8.x4.trans.shared.b16 {%0,%1,%2,%3}, [%4];"
                 : "=r"(r[0]), "=r"(r[1]), "=r"(r[2]), "=r"(r[3]) : "r"(a));
}
// split (a,b) -> packed bf16x2 hi word + lo word
__device__ __forceinline__ void split2(float a, float b, unsigned& h, unsigned& l) {
    bf16 ha = __float2bfloat16(a), hb = __float2bfloat16(b);
    bf16 la = __float2bfloat16(a - __bfloat162float(ha));
    bf16 lb = __float2bfloat16(b - __bfloat162float(hb));
    __nv_bfloat162 hh = __halves2bfloat162(ha, hb);
    __nv_bfloat162 ll = __halves2bfloat162(la, lb);
    h = *reinterpret_cast<unsigned*>(&hh);
    l = *reinterpret_cast<unsigned*>(&ll);
}

// ---------------- grid sample (bilinear, align_corners, zero pad) ----------
__global__ void __launch_bounds__(256)
k_gridsample(const float* __restrict__ uv, const float* __restrict__ feat,
             float* __restrict__ gs)
{
    const int b = blockIdx.x, c = threadIdx.x;
    const float* fb = feat + ((size_t)b * 256 + c) * 16;
    for (int p = 0; p < 64; ++p) {
        float gx = (uv[((size_t)b * 64 + p) * 2 + 0] - 0.5f) * 2.f;
        float gy = (uv[((size_t)b * 64 + p) * 2 + 1] - 0.5f) * 2.f;
        gx = fminf(fmaxf(gx, -1.f), 1.f);
        gy = fminf(fmaxf(gy, -1.f), 1.f);
        float x = (gx + 1.f) * 0.5f * 3.f;
        float y = (gy + 1.f) * 0.5f * 3.f;
        float x0f = floorf(x), y0f = floorf(y);
        int x0 = (int)x0f, y0 = (int)y0f;
        int x1 = x0 + 1, y1 = y0 + 1;
        float fx = x - x0f, fy = y - y0f;
        float wa = (1.f - fx) * (1.f - fy);
        float wb = (1.f - fx) * fy;
        float wc = fx * (1.f - fy);
        float wd = fx * fy;
        float Ia = (x0 >= 0 && x0 < 4 && y0 >= 0 && y0 < 4) ? fb[y0 * 4 + x0] : 0.f;
        float Ib = (x0 >= 0 && x0 < 4 && y1 >= 0 && y1 < 4) ? fb[y1 * 4 + x0] : 0.f;
        float Ic = (x1 >= 0 && x1 < 4 && y0 >= 0 && y0 < 4) ? fb[y0 * 4 + x1] : 0.f;
        float Id = (x1 >= 0 && x1 < 4 && y1 >= 0 && y1 < 4) ? fb[y1 * 4 + x1] : 0.f;
        gs[((size_t)b * 64 + p) * 256 + c] = Ia * wa + Ib * wb + Ic * wc + Id * wd;
    }
}

// ---------------- upsample GEMM: out[b,v,c] = sum_p up[v,p]*gs[b,p,c] ------
__global__ void __launch_bounds__(256)
k_upsample(const float* __restrict__ up, const float* __restrict__ gs,
           float* __restrict__ out)
{
    constexpr int VT = 16;
    __shared__ float up_s[VT][64];
    const int b = blockIdx.y, v0 = blockIdx.x * VT, c = threadIdx.x;
    for (int t = threadIdx.x; t < VT * 64; t += 256)
        up_s[t / 64][t % 64] = up[(size_t)(v0 + t / 64) * 64 + (t % 64)];
    __syncthreads();
    float acc[VT];
#pragma unroll
    for (int i = 0; i < VT; ++i) acc[i] = 0.f;
    for (int p = 0; p < 64; ++p) {
        float g = gs[((size_t)b * 64 + p) * 256 + c];
#pragma unroll
        for (int i = 0; i < VT; ++i) acc[i] = fmaf(up_s[i][p], g, acc[i]);
    }
#pragma unroll
    for (int i = 0; i < VT; ++i)
        out[((size_t)b * 784 + v0 + i) * 256 + c] = acc[i];
}

// ---------------- mesh up-pool ---------------------------------------------
template <int Ci>
__global__ void __launch_bounds__(256)
k_pool(const float4* __restrict__ x, const int* __restrict__ col,
       const float* __restrict__ val, float4* __restrict__ out,
       int Nin, int Nout)
{
    constexpr int CQ = Ci / 4;
    constexpr int VPB = 256 / CQ;
    const int b = blockIdx.y;
    const int n = blockIdx.x * VPB + threadIdx.x / CQ;
    const int cq = threadIdx.x % CQ;
    if (n >= Nout) return;
    const int c0 = col[3 * n + 0], c1 = col[3 * n + 1], c2 = col[3 * n + 2];
    const float v0 = val[3 * n + 0], v1 = val[3 * n + 1], v2 = val[3 * n + 2];
    const float4* xb = x + (size_t)b * Nin * CQ;
    float4 a = xb[(size_t)c0 * CQ + cq];
    float4 bb = xb[(size_t)c1 * CQ + cq];
    float4 cc = xb[(size_t)c2 * CQ + cq];
    float4 r;
    r.x = a.x * v0 + bb.x * v1 + cc.x * v2;
    r.y = a.y * v0 + bb.y * v1 + cc.y * v2;
    r.z = a.z * v0 + bb.z * v1 + cc.z * v2;
    r.w = a.w * v0 + bb.w * v1 + cc.w * v2;
    out[((size_t)b * Nout + n) * CQ + cq] = r;
}

// ---------------- fused pw pre-split ---------------------------------------
__global__ void __launch_bounds__(256)
k_splitw4(const float* __restrict__ w0, const float* __restrict__ w1,
          const float* __restrict__ w2, const float* __restrict__ w3,
          bf16* __restrict__ h, bf16* __restrict__ l)
{
    const int i = blockIdx.x * 256 + threadIdx.x;
    if (i >= 172032) return;
    float v;
    if (i < 65536)       v = w0[i];
    else if (i < 131072) v = w1[i - 65536];
    else if (i < 163840) v = w2[i - 131072];
    else                 v = w3[i - 163840];
    bf16 hh = __float2bfloat16(v);
    h[i] = hh;
    l[i] = __float2bfloat16(v - __bfloat162float(hh));
}

// ---------------- dw transpose: dwt[s][ci] = dw[ci][s] ---------------------
__global__ void __launch_bounds__(256)
k_dwt(const float* __restrict__ d0, const float* __restrict__ d1,
      const float* __restrict__ d2, const float* __restrict__ d3,
      float* __restrict__ out)
{
    const int i = blockIdx.x * 256 + threadIdx.x;
    if (i >= 8064) return;
    if (i < 2304)       { int j = i;        out[i] = d0[(j % 256) * SP + j / 256]; }
    else if (i < 4608)  { int j = i - 2304; out[i] = d1[(j % 256) * SP + j / 256]; }
    else if (i < 6912)  { int j = i - 4608; out[i] = d2[(j % 256) * SP + j / 256]; }
    else                { int j = i - 6912; out[i] = d3[(j % 128) * SP + j / 128]; }
}

// ---------------- FUSED gather + bf16-split tensor GEMM --------------------
// C[M,Co] = relu( (gather_dw(x))[M,K] @ pw[K,Co] ), M = B*N flat rows.
// 512 thr = 16 warps (WM x WN, WM*WN=16); TM=64; m16n8k16 bf16 mma.
// A-tile built per 32-k chunk directly from spiral gather (9 taps * dwt),
// split into bf16 hi/lo planes in smem.  3 mma terms: AhBh + AhBl + AlBh.
template <int K, int Co, int WM, int MT>
__global__ void __launch_bounds__(512, 1)
k_fused(const float* __restrict__ x, const int* __restrict__ idx,
        const float* __restrict__ dwt, const bf16* __restrict__ Bh,
        const bf16* __restrict__ Bl, float* __restrict__ C, int N)
{
    constexpr int WN = 16 / WM;
    constexpr int KK = 32;
    constexpr int NC = K / KK;
    constexpr int AST = KK + 8;          // 40
    constexpr int BST = Co + 8;
    constexpr int CW = Co / WN;          // cols per warp
    constexpr int P = CW / 16;           // 16-col ldsm groups per warp
    constexpr int NTW = CW / 8;
    constexpr int BCNT = KK * Co / 8;    // uint4 elements in B tile
    constexpr int BIT = (BCNT + 511) / 512;

    __shared__ bf16 Ah_s[64 * AST], Al_s[64 * AST];
    __shared__ bf16 Bh_s[KK * BST], Bl_s[KK * BST];
    __shared__ int idx_s[64 * SP];

    const int tid = threadIdx.x;
    const int lane = tid & 31;
    const int w = tid >> 5;
    const int wm = w / WN;
    const int wn = w % WN;
    const int m0 = blockIdx.x * 64;

    // stage spiral indices as flat global rows (b*N + idx[n][s])
    for (int t = tid; t < 64 * SP; t += 512) {
        const int mloc = t / SP, s = t - mloc * SP;
        const int g = m0 + mloc;
        const int b = g / N;
        const int n = g - b * N;
        idx_s[t] = b * N + idx[(size_t)n * SP + s];
    }
    __syncthreads();

    // gather thread map: 64 rows x 8 ci-quads
    const int gm = tid >> 3;
    const int gq = tid & 7;

    float4 acc[MT][NTW];
#pragma unroll
    for (int mt = 0; mt < MT; ++mt)
#pragma unroll
        for (int nt = 0; nt < NTW; ++nt)
            acc[mt][nt] = make_float4(0.f, 0.f, 0.f, 0.f);

    const int g8 = lane >> 3, rr = lane & 7;
    const int lk = lane & 3, lr = lane >> 2;

    for (int c = 0; c < NC; ++c) {
        const int kk = c * KK;

        // ---- gather A chunk (9 taps * dwt), fp32 accumulate ----
        float4 y = make_float4(0.f, 0.f, 0.f, 0.f);
        {
            const int co0 = kk + gq * 4;
            const int* iv = idx_s + gm * SP;
#pragma unroll
            for (int s = 0; s < SP; ++s) {
                const float4 xv = __ldg(reinterpret_cast<const float4*>(
                    x + (size_t)iv[s] * K + co0));
                const float4 dv = __ldg(reinterpret_cast<const float4*>(
                    dwt + s * K + co0));
                y.x = fmaf(xv.x, dv.x, y.x);
                y.y = fmaf(xv.y, dv.y, y.y);
                y.z = fmaf(xv.z, dv.z, y.z);
                y.w = fmaf(xv.w, dv.w, y.w);
            }
        }
        // ---- prefetch B chunk into regs ----
        uint4 brh[BIT], brl[BIT];
#pragma unroll
        for (int i = 0; i < BIT; ++i) {
            const int id = tid + i * 512;
            if (id < BCNT) {
                const int r = id / (Co / 8), nq = id % (Co / 8);
                const size_t off = (size_t)(kk + r) * Co + nq * 8;
                brh[i] = __ldg(reinterpret_cast<const uint4*>(Bh + off));
                brl[i] = __ldg(reinterpret_cast<const uint4*>(Bl + off));
            }
        }

        __syncthreads();   // prev chunk's ldsm complete

        // ---- store A (split) + B to smem ----
        {
            unsigned h0, l0, h1, l1;
            split2(y.x, y.y, h0, l0);
            split2(y.z, y.w, h1, l1);
            *reinterpret_cast<uint2*>(&Ah_s[gm * AST + gq * 4]) =
                make_uint2(h0, h1);
            *reinterpret_cast<uint2*>(&Al_s[gm * AST + gq * 4]) =
                make_uint2(l0, l1);
        }
#pragma unroll
        for (int i = 0; i < BIT; ++i) {
            const int id = tid + i * 512;
            if (id < BCNT) {
                const int r = id / (Co / 8), nq = id % (Co / 8);
                *reinterpret_cast<uint4*>(&Bh_s[r * BST + nq * 8]) = brh[i];
                *reinterpret_cast<uint4*>(&Bl_s[r * BST + nq * 8]) = brl[i];
            }
        }
        __syncthreads();

        // ---- MMA on chunk ----
#pragma unroll
        for (int ks = 0; ks < KK; ks += 16) {
            unsigned ah[MT][4], al[MT][4];
#pragma unroll
            for (int mt = 0; mt < MT; ++mt) {
                const int row = (wm * MT + mt) * 16 + (g8 & 1) * 8 + rr;
                const int col = ks + (g8 >> 1) * 8;
                ldsm4(ah[mt], &Ah_s[row * AST + col]);
                ldsm4(al[mt], &Al_s[row * AST + col]);
            }
#pragma unroll
            for (int p = 0; p < P; ++p) {
                unsigned bh[4], bl[4];
                const int krow = ks + (g8 & 1) * 8 + rr;
                const int ncol = wn * CW + p * 16 + (g8 >> 1) * 8;
                ldsm4t(bh, &Bh_s[krow * BST + ncol]);
                ldsm4t(bl, &Bl_s[krow * BST + ncol]);
#pragma unroll
                for (int mt = 0; mt < MT; ++mt) {
                    mma_bf16(acc[mt][2 * p], ah[mt], bh);
                    mma_bf16(acc[mt][2 * p], ah[mt], bl);
                    mma_bf16(acc[mt][2 * p], al[mt], bh);
                    mma_bf16(acc[mt][2 * p + 1], ah[mt], bh + 2);
                    mma_bf16(acc[mt][2 * p + 1], ah[mt], bl + 2);
                    mma_bf16(acc[mt][2 * p + 1], al[mt], bh + 2);
                }
            }
        }
    }

    // ---- epilogue: relu + store (flat rows) ----
#pragma unroll
    for (int mt = 0; mt < MT; ++mt) {
        const int rowl = (wm * MT + mt) * 16 + lr;
#pragma unroll
        for (int nt = 0; nt < NTW; ++nt) {
            const int colg = wn * CW + nt * 8 + 2 * lk;
            float2 o0 = make_float2(fmaxf(acc[mt][nt].x, 0.f),
                                    fmaxf(acc[mt][nt].y, 0.f));
            float2 o1 = make_float2(fmaxf(acc[mt][nt].z, 0.f),
                                    fmaxf(acc[mt][nt].w, 0.f));
            *reinterpret_cast<float2*>(
                C + (size_t)(m0 + rowl) * Co + colg) = o0;
            *reinterpret_cast<float2*>(
                C + (size_t)(m0 + rowl + 8) * Co + colg) = o1;
        }
    }
}

// ---------------- head: Ci=64 -> Co=3, float4 gathers ----------------------
__global__ void __launch_bounds__(256)
k_head(const float* __restrict__ x, const int* __restrict__ idx,
       const float* __restrict__ dw, const float* __restrict__ pw,
       float* __restrict__ out, int N)
{
    constexpr int Ci = 64;
    constexpr int VT = 64;
    constexpr int TPV = Ci / 4;
    constexpr int VG = 256 / TPV;
    constexpr int VCH = VT / VG;
    __shared__ __align__(16) float y_s[VT][Ci + 4];
    __shared__ float pw_s[Ci * 3];
    __shared__ int idx_s[VT * SP];
    const int b = blockIdx.y, n0 = blockIdx.x * VT, tid = threadIdx.x;

    if (tid < Ci * 3) pw_s[tid] = pw[tid];
    for (int t = tid; t < VT * SP; t += 256)
        idx_s[t] = idx[(size_t)n0 * SP + t];
    __syncthreads();

    {
        const int cq = (tid % TPV) * 4;
        const int vlo = (tid / TPV) * VCH;
        ull dw01[SP], dw23[SP];
#pragma unroll
        for (int s = 0; s < SP; ++s) {
            dw01[s] = pack2(__ldg(&dw[(size_t)(cq + 0) * SP + s]),
                            __ldg(&dw[(size_t)(cq + 1) * SP + s]));
            dw23[s] = pack2(__ldg(&dw[(size_t)(cq + 2) * SP + s]),
                            __ldg(&dw[(size_t)(cq + 3) * SP + s]));
        }
        const float* xb = x + ((size_t)b * N) * Ci + cq;
#pragma unroll 2
        for (int v = vlo; v < vlo + VCH; ++v) {
            const int* iv = idx_s + v * SP;
            ull a01 = 0ull, a23 = 0ull;
#pragma unroll
            for (int s = 0; s < SP; ++s) {
                float4 xv = *reinterpret_cast<const float4*>(
                    xb + (size_t)iv[s] * Ci);
                fma2(a01, pack2(xv.x, xv.y), dw01[s]);
                fma2(a23, pack2(xv.z, xv.w), dw23[s]);
            }
            float2 r01 = unpk(a01), r23 = unpk(a23);
            *reinterpret_cast<float4*>(&y_s[v][cq]) =
                make_float4(r01.x, r01.y, r23.x, r23.y);
        }
    }
    __syncthreads();

    if (tid < VT * 3) {
        const int v = tid / 3, co = tid % 3;
        float acc = 0.f;
#pragma unroll
        for (int ci = 0; ci < Ci; ++ci)
            acc = fmaf(y_s[v][ci], pw_s[ci * 3 + co], acc);
        out[((size_t)b * N + n0 + v) * 3 + co] = acc;
    }
}

// ---------------------------------------------------------------------------
extern "C" void kernel_launch(void* const* d_in, const int* in_sizes, int n_in,
                              void* d_out, int out_size)
{
    const float* uv   = (const float*)d_in[0];
    const float* feat = (const float*)d_in[1];
    const float* up   = (const float*)d_in[2];
    const float* dw0  = (const float*)d_in[3];
    const float* pw0  = (const float*)d_in[4];
    const float* dw1  = (const float*)d_in[5];
    const float* pw1  = (const float*)d_in[6];
    const float* dw2  = (const float*)d_in[7];
    const float* pw2  = (const float*)d_in[8];
    const float* dw3  = (const float*)d_in[9];
    const float* pw3  = (const float*)d_in[10];
    const float* dwh  = (const float*)d_in[11];
    const float* pwh  = (const float*)d_in[12];

    // Resolve input ordering ambiguity via element counts.
    const float *upv0, *upv1, *upv2, *upv3;
    const int *spi0, *spi1, *spi2, *spi3, *upc0, *upc1, *upc2, *upc3;
    if (in_sizes[13] == 37632) {
        upv0 = (const float*)d_in[13]; upv1 = (const float*)d_in[14];
        upv2 = (const float*)d_in[15]; upv3 = (const float*)d_in[16];
        spi0 = (const int*)d_in[17]; spi1 = (const int*)d_in[18];
        spi2 = (const int*)d_in[19]; spi3 = (const int*)d_in[20];
        upc0 = (const int*)d_in[21]; upc1 = (const int*)d_in[22];
        upc2 = (const int*)d_in[23]; upc3 = (const int*)d_in[24];
    } else {
        spi0 = (const int*)d_in[13]; upc0 = (const int*)d_in[14]; upv0 = (const float*)d_in[15];
        spi1 = (const int*)d_in[16]; upc1 = (const int*)d_in[17]; upv1 = (const float*)d_in[18];
        spi2 = (const int*)d_in[19]; upc2 = (const int*)d_in[20]; upv2 = (const float*)d_in[21];
        spi3 = (const int*)d_in[22]; upc3 = (const int*)d_in[23]; upv3 = (const float*)d_in[24];
    }

    float *gsP, *bufA, *bufB, *dwtP;
    bf16 *pwhP, *pwlP;
    cudaGetSymbolAddress((void**)&gsP, g_gs);
    cudaGetSymbolAddress((void**)&bufA, g_bufA);
    cudaGetSymbolAddress((void**)&bufB, g_bufB);
    cudaGetSymbolAddress((void**)&pwhP, g_pwh);
    cudaGetSymbolAddress((void**)&pwlP, g_pwl);
    cudaGetSymbolAddress((void**)&dwtP, g_dwt);
    float* outp = (float*)d_out;

    // pw split plane offsets (elements); dwt stage offsets
    const int O0 = 0, O1 = 65536, O2 = 131072, O3 = 163840;
    const int D0 = 0, D1 = 2304, D2 = 4608, D3 = 6912;
    k_splitw4<<<672, 256>>>(pw0, pw1, pw2, pw3, pwhP, pwlP);
    k_dwt<<<32, 256>>>(dw0, dw1, dw2, dw3, dwtP);

    // 1) grid sample; 2) upsample -> bufB (b,784,256)
    k_gridsample<<<B, 256>>>(uv, feat, gsP);
    k_upsample<<<dim3(49, B), 256>>>(up, gsP, bufB);

    // stage 0: pool 784->1568, fused gather(idx_3,dw0) + GEMM 256->256
    k_pool<256><<<dim3(1568 / 4, B), 256>>>((const float4*)bufB, upc3, upv3,
                                            (float4*)bufA, 784, 1568);
    k_fused<256, 256, 2, 2><<<B * 1568 / 64, 512>>>(
        bufA, spi3, dwtP + D0, pwhP + O0, pwlP + O0, bufB, 1568);

    // stage 1: pool 1568->3136, fused gather(idx_2,dw1) + GEMM 256->256
    k_pool<256><<<dim3(3136 / 4, B), 256>>>((const float4*)bufB, upc2, upv2,
                                            (float4*)bufA, 1568, 3136);
    k_fused<256, 256, 2, 2><<<B * 3136 / 64, 512>>>(
        bufA, spi2, dwtP + D1, pwhP + O1, pwlP + O1, bufB, 3136);

    // stage 2: pool 3136->6272, fused gather(idx_1,dw2) + GEMM 256->128
    k_pool<256><<<dim3(6272 / 4, B), 256>>>((const float4*)bufB, upc1, upv1,
                                            (float4*)bufA, 3136, 6272);
    k_fused<256, 128, 2, 2><<<B * 6272 / 64, 512>>>(
        bufA, spi1, dwtP + D2, pwhP + O2, pwlP + O2, bufB, 6272);

    // stage 3: pool 6272->12544 (Ci=128), fused gather(idx_0,dw3) + GEMM 128->64
    k_pool<128><<<dim3(12544 / 8, B), 256>>>((const float4*)bufB, upc0, upv0,
                                             (float4*)bufA, 6272, 12544);
    k_fused<128, 64, 4, 1><<<B * 12544 / 64, 512>>>(
        bufA, spi0, dwtP + D3, pwhP + O3, pwlP + O3, bufB, 12544);

    // head: Ci=64 -> 3, no relu
    k_head<<<dim3(12544 / 64, B), 256>>>(bufB, spi0, dwh, pwh, outp, 12544);
}